// round 6
// baseline (speedup 1.0000x reference)
#include <cuda_runtime.h>
#include <cuda_bf16.h>
#include <cstdint>

#define NUM_CHR 24
#define N_EMB   512
#define DIM     512
#define BATCH   1024

#define MT 64          // samples per tile
#define NT 128         // dims per tile
#define KB 16          // k-chunk through smem
#define KSPLIT 4
#define KCH (N_EMB / KSPLIT)   // 128 k per split
#define MTILES 2               // handles cnt > 64
#define NTILES (DIM / NT)      // 4

typedef unsigned long long ull;

// ---------------- scratch (device-code references only) ----------------
__device__ float g_W[BATCH * N_EMB];
__device__ int   g_order[BATCH];
__device__ int   g_start[NUM_CHR + 1];
__device__ float g_part[KSPLIT * BATCH * DIM];
__device__ int   g_ticket[NUM_CHR * MTILES * NTILES];   // zero-init, self-resetting

// ---------------- f32x2 helpers ----------------
__device__ __forceinline__ ull pack2(float lo, float hi) {
    ull r; asm("mov.b64 %0, {%1, %2};" : "=l"(r) : "f"(lo), "f"(hi)); return r;
}
__device__ __forceinline__ void unpack2(ull v, float& lo, float& hi) {
    asm("mov.b64 {%0, %1}, %2;" : "=f"(lo), "=f"(hi) : "l"(v));
}
__device__ __forceinline__ void ffma2(ull& d, ull a, ull b) {
    asm("fma.rn.f32x2 %0, %1, %2, %0;" : "+l"(d) : "l"(a), "l"(b));
}

// ---------------- kernel 1: weights (warp/sample) + grouping (last block) ---
__global__ void __launch_bounds__(256) weights_group_kernel(
    const int* __restrict__ chrom,
    const float* __restrict__ pos,
    const float* __restrict__ centers,
    const float* __restrict__ logv)
{
    if (blockIdx.x == BATCH / 8) {
        __shared__ int cnt[NUM_CHR];
        __shared__ int base[NUM_CHR];
        int t = threadIdx.x;
        if (t < NUM_CHR) cnt[t] = 0;
        __syncthreads();
        int cc[4], rr[4];
#pragma unroll
        for (int i = 0; i < 4; i++) {
            int b = i * 256 + t;
            cc[i] = chrom[b];
            rr[i] = atomicAdd(&cnt[cc[i]], 1);
        }
        __syncthreads();
        if (t == 0) {
            int acc = 0;
            for (int i = 0; i < NUM_CHR; i++) {
                base[i] = acc;
                g_start[i] = acc;
                acc += cnt[i];
            }
            g_start[NUM_CHR] = acc;
        }
        __syncthreads();
#pragma unroll
        for (int i = 0; i < 4; i++)
            g_order[base[cc[i]] + rr[i]] = i * 256 + t;
        return;
    }

    int warp = threadIdx.x >> 5, lane = threadIdx.x & 31;
    int b = blockIdx.x * 8 + warp;
    int c = chrom[b];
    float p = pos[b];

    const float* crow = centers + (size_t)c * N_EMB;
    const float* vrow = logv + (size_t)c * N_EMB;
    int n0 = lane * 16;

    float w[16];
    float s = 0.f;
#pragma unroll
    for (int i = 0; i < 4; i++) {
        float4 cc = *(const float4*)(crow + n0 + i * 4);
        float4 lv = *(const float4*)(vrow + n0 + i * 4);
        float d, iv;
        d = p - cc.x; iv = __expf(-lv.x); w[i*4+0] = __expf(-0.5f * d * d * iv);
        d = p - cc.y; iv = __expf(-lv.y); w[i*4+1] = __expf(-0.5f * d * d * iv);
        d = p - cc.z; iv = __expf(-lv.z); w[i*4+2] = __expf(-0.5f * d * d * iv);
        d = p - cc.w; iv = __expf(-lv.w); w[i*4+3] = __expf(-0.5f * d * d * iv);
        s += w[i*4+0] + w[i*4+1] + w[i*4+2] + w[i*4+3];
    }
#pragma unroll
    for (int off = 16; off > 0; off >>= 1)
        s += __shfl_xor_sync(0xffffffffu, s, off);
    float inv = 1.f / s;

    float* wrow = g_W + (size_t)b * N_EMB + n0;
#pragma unroll
    for (int i = 0; i < 4; i++) {
        *(float4*)(wrow + i * 4) = make_float4(w[i*4+0] * inv, w[i*4+1] * inv,
                                               w[i*4+2] * inv, w[i*4+3] * inv);
    }
}

// ---------------- kernel 2: grouped GEMM + fused split-K reduction ---------
__global__ void __launch_bounds__(128) gemm_kernel(const float* __restrict__ E,
                                                   float* __restrict__ out)
{
    int c  = blockIdx.z;
    int nt = blockIdx.x;
    int ks = blockIdx.y >> 1;
    int mt = blockIdx.y & 1;

    __shared__ __align__(16) float As[KB][MT];
    __shared__ __align__(16) float Bs[KB][NT];
    __shared__ int sord[MT];
    __shared__ int s_ticket;

    int tid = threadIdx.x;
    int d0  = nt * NT;
    int kbase = ks * KCH;

    // ---- B prefetch for first chunk: depends only on blockIdx, runs under PDL
    const float* Eb0 = E + ((size_t)c * N_EMB + kbase) * DIM + d0;
#pragma unroll
    for (int j = 0; j < 4; j++) {
        int f  = j * 128 + tid;
        int r  = f >> 5;
        int c4 = (f & 31) * 4;
        *(float4*)&Bs[r][c4] = *(const float4*)(Eb0 + (size_t)r * DIM + c4);
    }

    // ---- wait for weights/grouping kernel ----
    cudaGridDependencySynchronize();

    int s0  = g_start[c];
    int cnt = g_start[c + 1] - s0;
    int m0  = mt * MT;
    if (m0 >= cnt) return;

    if (tid < MT) {
        int g = m0 + tid;
        sord[tid] = (g < cnt) ? g_order[s0 + g] : -1;
    }
    __syncthreads();

    int am = tid & 63;
    int ak = (tid >> 6) * 8;
    int samp = sord[am];
    const float* wrow = (samp >= 0) ? (g_W + (size_t)samp * N_EMB) : g_W;

    int tx = tid & 15;
    int ty = tid >> 4;

    ull acc[8][4];
#pragma unroll
    for (int i = 0; i < 8; i++)
#pragma unroll
        for (int j = 0; j < 4; j++) acc[i][j] = 0ull;

    for (int k0 = kbase; k0 < kbase + KCH; k0 += KB) {
        // A tile
        if (samp >= 0) {
            float4 v0 = *(const float4*)(wrow + k0 + ak + 0);
            float4 v1 = *(const float4*)(wrow + k0 + ak + 4);
            As[ak + 0][am] = v0.x; As[ak + 1][am] = v0.y;
            As[ak + 2][am] = v0.z; As[ak + 3][am] = v0.w;
            As[ak + 4][am] = v1.x; As[ak + 5][am] = v1.y;
            As[ak + 6][am] = v1.z; As[ak + 7][am] = v1.w;
        } else {
#pragma unroll
            for (int j = 0; j < 8; j++) As[ak + j][am] = 0.f;
        }
        // B tile (first chunk already prefetched)
        if (k0 != kbase) {
            const float* Eb = E + ((size_t)c * N_EMB + k0) * DIM + d0;
#pragma unroll
            for (int j = 0; j < 4; j++) {
                int f  = j * 128 + tid;
                int r  = f >> 5;
                int c4 = (f & 31) * 4;
                *(float4*)&Bs[r][c4] = *(const float4*)(Eb + (size_t)r * DIM + c4);
            }
        }
        __syncthreads();

#pragma unroll
        for (int kk = 0; kk < KB; kk++) {
            float4 alo = *(const float4*)&As[kk][ty * 4];
            float4 ahi = *(const float4*)&As[kk][32 + ty * 4];
            ull a[8];
            a[0] = pack2(alo.x, alo.x); a[1] = pack2(alo.y, alo.y);
            a[2] = pack2(alo.z, alo.z); a[3] = pack2(alo.w, alo.w);
            a[4] = pack2(ahi.x, ahi.x); a[5] = pack2(ahi.y, ahi.y);
            a[6] = pack2(ahi.z, ahi.z); a[7] = pack2(ahi.w, ahi.w);
            const ull* blo = (const ull*)&Bs[kk][tx * 4];
            const ull* bhi = (const ull*)&Bs[kk][64 + tx * 4];
            ull b0 = blo[0], b1 = blo[1], b2 = bhi[0], b3 = bhi[1];
#pragma unroll
            for (int i = 0; i < 8; i++) {
                ffma2(acc[i][0], a[i], b0);
                ffma2(acc[i][1], a[i], b1);
                ffma2(acc[i][2], a[i], b2);
                ffma2(acc[i][3], a[i], b3);
            }
        }
        __syncthreads();
    }

    // ---- write split-K partials ----
    float* pbase = g_part + (size_t)ks * BATCH * DIM;
#pragma unroll
    for (int half = 0; half < 2; half++) {
#pragma unroll
        for (int i = 0; i < 4; i++) {
            int mi  = half * 32 + ty * 4 + i;
            int gmi = m0 + mi;
            if (gmi < cnt) {
                int b = sord[mi];
                float x0, x1, x2, x3, y0, y1, y2, y3;
                unpack2(acc[half * 4 + i][0], x0, x1);
                unpack2(acc[half * 4 + i][1], x2, x3);
                unpack2(acc[half * 4 + i][2], y0, y1);
                unpack2(acc[half * 4 + i][3], y2, y3);
                float* orow = pbase + (size_t)b * DIM + d0;
                *(float4*)(orow + tx * 4)      = make_float4(x0, x1, x2, x3);
                *(float4*)(orow + 64 + tx * 4) = make_float4(y0, y1, y2, y3);
            }
        }
    }

    // ---- ticket: last ks-block for this (c, mt, nt) tile does the reduction
    int tile_id = (c * MTILES + mt) * NTILES + nt;
    __threadfence();
    __syncthreads();
    if (tid == 0) s_ticket = atomicAdd(&g_ticket[tile_id], 1);
    __syncthreads();
    if (s_ticket != KSPLIT - 1) return;

    if (tid == 0) g_ticket[tile_id] = 0;   // self-reset for next replay
    __threadfence();                        // acquire other planes' stores

    const size_t S = (size_t)BATCH * DIM;
#pragma unroll
    for (int half = 0; half < 2; half++) {
#pragma unroll
        for (int i = 0; i < 4; i++) {
            int mi  = half * 32 + ty * 4 + i;
            int gmi = m0 + mi;
            if (gmi < cnt) {
                int b = sord[mi];
                const float* prow = g_part + (size_t)b * DIM + d0;
#pragma unroll
                for (int col = 0; col < 2; col++) {
                    const float* pp = prow + col * 64 + tx * 4;
                    float4 p0 = *(const float4*)(pp);
                    float4 p1 = *(const float4*)(pp + S);
                    float4 p2 = *(const float4*)(pp + 2 * S);
                    float4 p3 = *(const float4*)(pp + 3 * S);
                    *(float4*)(out + (size_t)b * DIM + d0 + col * 64 + tx * 4) =
                        make_float4((p0.x + p1.x) + (p2.x + p3.x),
                                    (p0.y + p1.y) + (p2.y + p3.y),
                                    (p0.z + p1.z) + (p2.z + p3.z),
                                    (p0.w + p1.w) + (p2.w + p3.w));
                }
            }
        }
    }
}

// ---------------- launch ----------------
extern "C" void kernel_launch(void* const* d_in, const int* in_sizes, int n_in,
                              void* d_out, int out_size)
{
    const int*   chrom    = (const int*)d_in[0];
    const float* position = (const float*)d_in[1];
    const float* embed    = (const float*)d_in[2];
    const float* centers  = (const float*)d_in[3];
    const float* logv     = (const float*)d_in[4];
    float*       out      = (float*)d_out;

    weights_group_kernel<<<BATCH / 8 + 1, 256>>>(chrom, position, centers, logv);

    dim3 grid(NTILES, KSPLIT * MTILES, NUM_CHR);   // (4, 8, 24)
    cudaLaunchAttribute attr[1];
    attr[0].id = cudaLaunchAttributeProgrammaticStreamSerialization;
    attr[0].val.programmaticStreamSerializationAllowed = 1;
    cudaLaunchConfig_t cfg{};
    cfg.gridDim = grid;
    cfg.blockDim = dim3(128, 1, 1);
    cfg.dynamicSmemBytes = 0;
    cfg.stream = 0;
    cfg.attrs = attr;
    cfg.numAttrs = 1;
    cudaLaunchKernelEx(&cfg, gemm_kernel, embed, out);
}

// round 7
// speedup vs baseline: 1.2474x; 1.2474x over previous
#include <cuda_runtime.h>
#include <cuda_bf16.h>
#include <cstdint>

#define NUM_CHR 24
#define N_EMB   512
#define DIM     512
#define BATCH   1024

#define MT 64          // samples per tile
#define NT 128         // dims per tile
#define KB 16          // k-chunk through smem
#define KSPLIT 4
#define KCH (N_EMB / KSPLIT)   // 128 k per split
#define MTILES 2               // handles cnt > 64
#define NTILES (DIM / NT)      // 4

typedef unsigned long long ull;

// ---------------- scratch (device-code references only) ----------------
__device__ float g_W[BATCH * N_EMB];
__device__ int   g_order[BATCH];
__device__ int   g_start[NUM_CHR + 1];
__device__ float g_part[KSPLIT * BATCH * DIM];

// ---------------- f32x2 helpers ----------------
__device__ __forceinline__ ull pack2(float lo, float hi) {
    ull r; asm("mov.b64 %0, {%1, %2};" : "=l"(r) : "f"(lo), "f"(hi)); return r;
}
__device__ __forceinline__ void unpack2(ull v, float& lo, float& hi) {
    asm("mov.b64 {%0, %1}, %2;" : "=f"(lo), "=f"(hi) : "l"(v));
}
__device__ __forceinline__ void ffma2(ull& d, ull a, ull b) {
    asm("fma.rn.f32x2 %0, %1, %2, %0;" : "+l"(d) : "l"(a), "l"(b));
}

// ---------------- kernel 1: weights (warp/sample) + grouping (last block) ---
__global__ void __launch_bounds__(256) weights_group_kernel(
    const int* __restrict__ chrom,
    const float* __restrict__ pos,
    const float* __restrict__ centers,
    const float* __restrict__ logv)
{
    if (blockIdx.x == BATCH / 8) {
        __shared__ int cnt[NUM_CHR];
        __shared__ int base[NUM_CHR];
        int t = threadIdx.x;
        if (t < NUM_CHR) cnt[t] = 0;
        __syncthreads();
        int cc[4], rr[4];
#pragma unroll
        for (int i = 0; i < 4; i++) {
            int b = i * 256 + t;
            cc[i] = chrom[b];
            rr[i] = atomicAdd(&cnt[cc[i]], 1);
        }
        __syncthreads();
        if (t == 0) {
            int acc = 0;
            for (int i = 0; i < NUM_CHR; i++) {
                base[i] = acc;
                g_start[i] = acc;
                acc += cnt[i];
            }
            g_start[NUM_CHR] = acc;
        }
        __syncthreads();
#pragma unroll
        for (int i = 0; i < 4; i++)
            g_order[base[cc[i]] + rr[i]] = i * 256 + t;
        return;
    }

    int warp = threadIdx.x >> 5, lane = threadIdx.x & 31;
    int b = blockIdx.x * 8 + warp;
    int c = chrom[b];
    float p = pos[b];

    const float* crow = centers + (size_t)c * N_EMB;
    const float* vrow = logv + (size_t)c * N_EMB;
    int n0 = lane * 16;

    float w[16];
    float s = 0.f;
#pragma unroll
    for (int i = 0; i < 4; i++) {
        float4 cc = *(const float4*)(crow + n0 + i * 4);
        float4 lv = *(const float4*)(vrow + n0 + i * 4);
        float d, iv;
        d = p - cc.x; iv = __expf(-lv.x); w[i*4+0] = __expf(-0.5f * d * d * iv);
        d = p - cc.y; iv = __expf(-lv.y); w[i*4+1] = __expf(-0.5f * d * d * iv);
        d = p - cc.z; iv = __expf(-lv.z); w[i*4+2] = __expf(-0.5f * d * d * iv);
        d = p - cc.w; iv = __expf(-lv.w); w[i*4+3] = __expf(-0.5f * d * d * iv);
        s += w[i*4+0] + w[i*4+1] + w[i*4+2] + w[i*4+3];
    }
#pragma unroll
    for (int off = 16; off > 0; off >>= 1)
        s += __shfl_xor_sync(0xffffffffu, s, off);
    float inv = 1.f / s;

    float* wrow = g_W + (size_t)b * N_EMB + n0;
#pragma unroll
    for (int i = 0; i < 4; i++) {
        *(float4*)(wrow + i * 4) = make_float4(w[i*4+0] * inv, w[i*4+1] * inv,
                                               w[i*4+2] * inv, w[i*4+3] * inv);
    }
}

// ---------------- kernel 2: grouped GEMM, split-K ----------------
// Block M64 x N128 x K128, 256 threads, micro-tile 8m x 4n.
// tx = tid&31 (n: tx*4), ty = tid>>5 (m: ty*4+{0..3} and 32+ty*4+{0..3}).
__global__ void __launch_bounds__(256, 3) gemm_kernel(const float* __restrict__ E)
{
    int c  = blockIdx.z;
    int nt = blockIdx.x;
    int ks = blockIdx.y >> 1;
    int mt = blockIdx.y & 1;

    int s0  = g_start[c];
    int cnt = g_start[c + 1] - s0;
    int m0  = mt * MT;
    if (m0 >= cnt) return;

    __shared__ __align__(16) float As[KB][MT];
    __shared__ __align__(16) float Bs[KB][NT];
    __shared__ int sord[MT];

    int tid = threadIdx.x;
    int d0  = nt * NT;

    if (tid < MT) {
        int g = m0 + tid;
        sord[tid] = (g < cnt) ? g_order[s0 + g] : -1;
    }
    __syncthreads();

    // A-load: thread -> (m row 0..63, 4-wide k quarter)
    int am = tid & 63;
    int ak = (tid >> 6) * 4;      // 0,4,8,12
    int samp = sord[am];
    const float* wrow = (samp >= 0) ? (g_W + (size_t)samp * N_EMB) : g_W;

    int tx = tid & 31;
    int ty = tid >> 5;

    ull acc[8][2];
#pragma unroll
    for (int i = 0; i < 8; i++) { acc[i][0] = 0ull; acc[i][1] = 0ull; }

    int kbase = ks * KCH;
    for (int k0 = kbase; k0 < kbase + KCH; k0 += KB) {
        // ---- A tile: one float4 per thread ----
        if (samp >= 0) {
            float4 v = *(const float4*)(wrow + k0 + ak);
            As[ak + 0][am] = v.x; As[ak + 1][am] = v.y;
            As[ak + 2][am] = v.z; As[ak + 3][am] = v.w;
        } else {
#pragma unroll
            for (int j = 0; j < 4; j++) As[ak + j][am] = 0.f;
        }
        // ---- B tile: 2 float4 per thread, coalesced ----
        const float* Eb = E + ((size_t)c * N_EMB + k0) * DIM + d0;
#pragma unroll
        for (int j = 0; j < 2; j++) {
            int f  = j * 256 + tid;      // 0..511 flat float4 index
            int r  = f >> 5;             // k row 0..15
            int c4 = (f & 31) * 4;       // col 0..124
            *(float4*)&Bs[r][c4] = *(const float4*)(Eb + (size_t)r * DIM + c4);
        }
        __syncthreads();

        // ---- compute ----
#pragma unroll
        for (int kk = 0; kk < KB; kk++) {
            float4 alo = *(const float4*)&As[kk][ty * 4];        // warp-broadcast
            float4 ahi = *(const float4*)&As[kk][32 + ty * 4];   // warp-broadcast
            const ull* bp = (const ull*)&Bs[kk][tx * 4];
            ull b0 = bp[0], b1 = bp[1];
            ull a0 = pack2(alo.x, alo.x), a1 = pack2(alo.y, alo.y);
            ull a2 = pack2(alo.z, alo.z), a3 = pack2(alo.w, alo.w);
            ull a4 = pack2(ahi.x, ahi.x), a5 = pack2(ahi.y, ahi.y);
            ull a6 = pack2(ahi.z, ahi.z), a7 = pack2(ahi.w, ahi.w);
            ffma2(acc[0][0], a0, b0); ffma2(acc[0][1], a0, b1);
            ffma2(acc[1][0], a1, b0); ffma2(acc[1][1], a1, b1);
            ffma2(acc[2][0], a2, b0); ffma2(acc[2][1], a2, b1);
            ffma2(acc[3][0], a3, b0); ffma2(acc[3][1], a3, b1);
            ffma2(acc[4][0], a4, b0); ffma2(acc[4][1], a4, b1);
            ffma2(acc[5][0], a5, b0); ffma2(acc[5][1], a5, b1);
            ffma2(acc[6][0], a6, b0); ffma2(acc[6][1], a6, b1);
            ffma2(acc[7][0], a7, b0); ffma2(acc[7][1], a7, b1);
        }
        __syncthreads();
    }

    // ---- epilogue -> split-K partials ----
    float* pbase = g_part + (size_t)ks * BATCH * DIM;
#pragma unroll
    for (int i = 0; i < 8; i++) {
        int mi  = (i < 4) ? (ty * 4 + i) : (32 + ty * 4 + (i - 4));
        int gmi = m0 + mi;
        if (gmi < cnt) {
            int b = sord[mi];
            float x0, x1, x2, x3;
            unpack2(acc[i][0], x0, x1);
            unpack2(acc[i][1], x2, x3);
            *(float4*)(pbase + (size_t)b * DIM + d0 + tx * 4) =
                make_float4(x0, x1, x2, x3);
        }
    }
}

// ---------------- kernel 3: fixed-order split-K reduce ----------------
// 2 float4 output elements per thread, 8 plane-loads in flight (MLP 8).
__global__ void __launch_bounds__(256) reduce_kernel(float* __restrict__ out)
{
    int i = (blockIdx.x * 256 + threadIdx.x) * 8;
    const size_t S = (size_t)BATCH * DIM;
    float4 a0 = *(const float4*)(g_part + i);
    float4 a1 = *(const float4*)(g_part + i + 4);
    float4 b0 = *(const float4*)(g_part + S + i);
    float4 b1 = *(const float4*)(g_part + S + i + 4);
    float4 c0 = *(const float4*)(g_part + 2 * S + i);
    float4 c1 = *(const float4*)(g_part + 2 * S + i + 4);
    float4 d0 = *(const float4*)(g_part + 3 * S + i);
    float4 d1 = *(const float4*)(g_part + 3 * S + i + 4);
    *(float4*)(out + i) = make_float4(
        (a0.x + b0.x) + (c0.x + d0.x),
        (a0.y + b0.y) + (c0.y + d0.y),
        (a0.z + b0.z) + (c0.z + d0.z),
        (a0.w + b0.w) + (c0.w + d0.w));
    *(float4*)(out + i + 4) = make_float4(
        (a1.x + b1.x) + (c1.x + d1.x),
        (a1.y + b1.y) + (c1.y + d1.y),
        (a1.z + b1.z) + (c1.z + d1.z),
        (a1.w + b1.w) + (c1.w + d1.w));
}

// ---------------- launch ----------------
extern "C" void kernel_launch(void* const* d_in, const int* in_sizes, int n_in,
                              void* d_out, int out_size)
{
    const int*   chrom    = (const int*)d_in[0];
    const float* position = (const float*)d_in[1];
    const float* embed    = (const float*)d_in[2];
    const float* centers  = (const float*)d_in[3];
    const float* logv     = (const float*)d_in[4];
    float*       out      = (float*)d_out;

    weights_group_kernel<<<BATCH / 8 + 1, 256>>>(chrom, position, centers, logv);

    dim3 grid(NTILES, KSPLIT * MTILES, NUM_CHR);   // (4, 8, 24)
    gemm_kernel<<<grid, 256>>>(embed);

    reduce_kernel<<<BATCH * DIM / (256 * 8), 256>>>(out);
}